// round 13
// baseline (speedup 1.0000x reference)
#include <cuda_runtime.h>
#include <math_constants.h>

#define BATCH 16
#define H 1024
#define W 1024
#define HW (H * W)
#define TOPKN 512
#define CAP 131072

static __device__ float g_scores[(size_t)BATCH * HW];
static __device__ int g_ncand[BATCH];
static __device__ unsigned long long g_keys[BATCH][CAP];

__device__ __forceinline__ unsigned int ford(float f) {
    unsigned int u = __float_as_uint(f);
    return (u & 0x80000000u) ? ~u : (u | 0x80000000u);
}
__device__ __forceinline__ float finv(unsigned int u) {
    u = (u & 0x80000000u) ? (u & 0x7fffffffu) : ~u;
    return __uint_as_float(u);
}
__device__ __forceinline__ float shi_tomasi(int A, int Bv, int C) {
    float fa = (float)A, fc = (float)C, fb = (float)Bv;
    float dd = __fsub_rn(fa, fc);
    float s  = __fadd_rn(__fmul_rn(dd, dd), __fmul_rn(__fmul_rn(4.0f, fb), fb));
    return 0.5f * __fsub_rn(__fadd_rn(fa, fc), __fsqrt_rn(s));
}

// ===========================================================================
// K1: separable vectorized response. 32x32 tile, 256 threads.
//  S1: img -> smem int (40x40, halo 4)
//  S2: pq = pack(p = vert [1,2,1], q = vert diff) (38 rows x 40 cols)
//  S3: grads from pq + horizontal 7-sums, 4 cols/thread, int4 stores
//  S4: vertical 7-sum via int4 loads, resp, float4 store
// ===========================================================================
__global__ __launch_bounds__(256) void k1_response(const float* __restrict__ im) {
    const int b = blockIdx.z;
    const int tx0 = blockIdx.x * 32, ty0 = blockIdx.y * 32;
    __shared__ __align__(16) int simg[40][41];
    __shared__ __align__(16) unsigned spq[38][41];
    __shared__ __align__(16) int shA[38][36];
    __shared__ __align__(16) int shB[38][36];
    __shared__ __align__(16) int shC[38][36];
    const int t = threadIdx.x;
    const float* imb = im + (size_t)b * HW;

    // S1: quantized image, zero outside domain
    for (int i = t; i < 1600; i += 256) {
        int r = i / 40, c = i % 40;
        int yy = ty0 - 4 + r, xx = tx0 - 4 + c;
        int v = 0;
        if ((unsigned)yy < H && (unsigned)xx < W)
            v = __float2int_rd(imb[yy * W + xx] * 255.0f);
        simg[r][c] = v;
    }
    __syncthreads();

    // S2: vertical smooth p and diff q, packed (q<<16)|(p&0xFFFF)
    for (int i = t; i < 1520; i += 256) {
        int r = i / 40, c = i % 40;
        int a = simg[r][c], m = simg[r + 1][c], d2 = simg[r + 2][c];
        int p = a + 2 * m + d2;          // 0..1020
        int q = d2 - a;                  // -510..510
        spq[r][c] = (unsigned)((q << 16) | (p & 0xFFFF));
    }
    __syncthreads();

    // S3: 304 tasks = 38 grad-rows x 8 col-chunks of 4
    for (int i = t; i < 304; i += 256) {
        int r = i >> 3, ch = i & 7;
        int j0 = ch << 2;
        int4 hA4 = make_int4(0, 0, 0, 0);
        int4 hB4 = hA4, hC4 = hA4;
        if ((unsigned)(ty0 - 3 + r) < H) {
            unsigned pq[12];
#pragma unroll
            for (int k = 0; k < 12; k++) pq[k] = spq[r][j0 + k];
            int A[10], Bv[10], C[10];
#pragma unroll
            for (int g = 0; g < 10; g++) {
                int pm = (int)(pq[g] & 0xFFFFu);
                int pp = (int)(pq[g + 2] & 0xFFFFu);
                int qm = ((int)pq[g]) >> 16;
                int q0 = ((int)pq[g + 1]) >> 16;
                int qp = ((int)pq[g + 2]) >> 16;
                int gx = pp - pm;                 // sobel x at img col tx0-3+j0+g
                int gy = qm + 2 * q0 + qp;        // sobel y
                bool ok = ((unsigned)(tx0 - 3 + j0 + g) < W);
                A[g]  = ok ? gx * gx : 0;
                Bv[g] = ok ? gx * gy : 0;
                C[g]  = ok ? gy * gy : 0;
            }
            int s0, s1, s2, s3;
            s0 = A[0] + A[1] + A[2] + A[3] + A[4] + A[5] + A[6];
            s1 = s0 - A[0] + A[7]; s2 = s1 - A[1] + A[8]; s3 = s2 - A[2] + A[9];
            hA4 = make_int4(s0, s1, s2, s3);
            s0 = Bv[0] + Bv[1] + Bv[2] + Bv[3] + Bv[4] + Bv[5] + Bv[6];
            s1 = s0 - Bv[0] + Bv[7]; s2 = s1 - Bv[1] + Bv[8]; s3 = s2 - Bv[2] + Bv[9];
            hB4 = make_int4(s0, s1, s2, s3);
            s0 = C[0] + C[1] + C[2] + C[3] + C[4] + C[5] + C[6];
            s1 = s0 - C[0] + C[7]; s2 = s1 - C[1] + C[8]; s3 = s2 - C[2] + C[9];
            hC4 = make_int4(s0, s1, s2, s3);
        }
        *(int4*)&shA[r][j0] = hA4;
        *(int4*)&shB[r][j0] = hB4;
        *(int4*)&shC[r][j0] = hC4;
    }
    __syncthreads();

    // S4: vertical 7-sum, 4 outputs per thread (row = t>>3, cols (t&7)*4 ..)
    {
        int r = t >> 3;
        int j0 = (t & 7) << 2;
        int sa0 = 0, sa1 = 0, sa2 = 0, sa3 = 0;
        int sb0 = 0, sb1 = 0, sb2 = 0, sb3 = 0;
        int sc0 = 0, sc1 = 0, sc2 = 0, sc3 = 0;
#pragma unroll
        for (int k = 0; k < 7; k++) {
            int4 a4 = *(const int4*)&shA[r + k][j0];
            int4 b4 = *(const int4*)&shB[r + k][j0];
            int4 c4 = *(const int4*)&shC[r + k][j0];
            sa0 += a4.x; sa1 += a4.y; sa2 += a4.z; sa3 += a4.w;
            sb0 += b4.x; sb1 += b4.y; sb2 += b4.z; sb3 += b4.w;
            sc0 += c4.x; sc1 += c4.y; sc2 += c4.z; sc3 += c4.w;
        }
        float4 o;
        o.x = shi_tomasi(sa0, sb0, sc0);
        o.y = shi_tomasi(sa1, sb1, sc1);
        o.z = shi_tomasi(sa2, sb2, sc2);
        o.w = shi_tomasi(sa3, sb3, sc3);
        *(float4*)(g_scores + (size_t)b * HW + (size_t)(ty0 + r) * W + tx0 + j0) = o;
    }
}

// ===========================================================================
// K2: pyramid NMS with clamped loads + warp-ballot compaction + batch emit.
// ===========================================================================
#define SURVCAP 768
#define WINCAP 64

__global__ __launch_bounds__(256) void k2_nms() {
    const int b = blockIdx.z;
    const int X0 = blockIdx.x * 32, Y0 = blockIdx.y * 32;
    __shared__ __align__(16) float sr[46][48];
    __shared__ __align__(16) float h3[46][48];
    __shared__ __align__(16) float m3[44][48];
    __shared__ float sv[SURVCAP];
    __shared__ int spos[SURVCAP];
    __shared__ unsigned long long wk[WINCAP];
    __shared__ int scount;
    __shared__ int wcount;
    __shared__ int s_base;
    const int t = threadIdx.x;
    const float* rbase = g_scores + (size_t)b * HW;

    if (t == 0) { scount = 0; wcount = 0; }
    // clamped loads: window-max under index clamping == -inf-padded window max
    for (int i = t; i < 46 * 46; i += 256) {
        int r = i / 46, c = i % 46;
        int gy = min(max(Y0 - 7 + r, 0), H - 1);
        int gx = min(max(X0 - 7 + c, 0), W - 1);
        sr[r][c] = rbase[gy * W + gx];
    }
    __syncthreads();

    for (int i = t; i < 46 * 22; i += 256) {
        int r = i / 22, x = 2 * (i % 22);
        float2 f0 = *(float2*)&sr[r][x];
        float2 f1 = *(float2*)&sr[r][x + 2];
        float h0 = fmaxf(f0.x, fmaxf(f0.y, f1.x));
        float h1 = fmaxf(f0.y, fmaxf(f1.x, f1.y));
        *(float2*)&h3[r][x] = make_float2(h0, h1);
    }
    __syncthreads();

    for (int i = t; i < 44 * 22; i += 256) {
        int r = i / 22, x = 2 * (i % 22);
        float2 a  = *(float2*)&h3[r][x];
        float2 bb = *(float2*)&h3[r + 1][x];
        float2 cc = *(float2*)&h3[r + 2][x];
        float m0 = fmaxf(a.x, fmaxf(bb.x, cc.x));
        float m1 = fmaxf(a.y, fmaxf(bb.y, cc.y));
        *(float2*)&m3[r][x] = make_float2(m0, m1);
    }
    __syncthreads();

    // prune (ballot-compacted): candidate must be >= its 3x3 max
#pragma unroll
    for (int it = 0; it < 4; it++) {
        int i = it * 256 + t;
        int r = i >> 5, c = i & 31;
        float v = sr[r + 7][c + 7];
        bool pred = (v >= m3[r + 6][c + 6]);
        unsigned mask = __ballot_sync(0xffffffffu, pred);
        int cnt = __popc(mask);
        int base = 0;
        if ((t & 31) == 0 && cnt > 0) base = atomicAdd(&scount, cnt);
        base = __shfl_sync(0xffffffffu, base, 0);
        if (pred) {
            int s = base + __popc(mask & ((1u << (t & 31)) - 1u));
            if (s < SURVCAP) { sv[s] = v; spos[s] = (r << 5) | c; }
        }
    }
    __syncthreads();

    // verify survivors vs exact 15x15 max (5x5 stride-3 grid of m3)
    int sc = scount < SURVCAP ? scount : SURVCAP;
    int iters = (sc + 255) >> 8;
    for (int it = 0; it < iters; it++) {
        int i = it * 256 + t;
        bool win = false;
        float v = 0.0f; int r = 0, c = 0;
        if (i < sc) {
            v = sv[i];
            int rc = spos[i];
            r = rc >> 5; c = rc & 31;
            float m = -CUDART_INF_F;
#pragma unroll
            for (int di = 0; di < 5; di++)
#pragma unroll
                for (int dj = 0; dj < 5; dj++)
                    m = fmaxf(m, m3[r + 3 * di][c + 3 * dj]);
            win = (v >= m);
        }
        unsigned mask = __ballot_sync(0xffffffffu, win);
        int cnt = __popc(mask);
        int base = 0;
        if ((t & 31) == 0 && cnt > 0) base = atomicAdd(&wcount, cnt);
        base = __shfl_sync(0xffffffffu, base, 0);
        if (win) {
            int w = base + __popc(mask & ((1u << (t & 31)) - 1u));
            if (w < WINCAP) {
                unsigned int idx = (unsigned)((Y0 + r) * W + (X0 + c));
                wk[w] = ((unsigned long long)ford(v) << 32) | (unsigned int)(~idx);
            }
        }
    }
    __syncthreads();

    int nw = wcount < WINCAP ? wcount : WINCAP;
    if (t == 0 && nw > 0) s_base = atomicAdd(&g_ncand[b], nw);
    __syncthreads();
    if (nw > 0) {
        int base = s_base;
        for (int i = t; i < nw; i += 256) {
            int slot = base + i;
            if (slot < CAP) g_keys[b][slot] = wk[i];
        }
    }
}

// ===========================================================================
// K3: candidate max -> threshold; exact top-512 via 6-pass histogram radix
// select; bitonic sort; threshold applied at output; counter self-reset.
// ===========================================================================
__global__ __launch_bounds__(512) void k3_topk(float* __restrict__ out, int write_coords) {
    const int b = blockIdx.x;
    const int t = threadIdx.x;
    __shared__ int hist[2048];
    __shared__ int s_sth[512];
    __shared__ int s_ws[16];
    __shared__ unsigned int s_mx[16];
    __shared__ unsigned long long skeys[TOPKN];
    __shared__ unsigned long long s_prefix;
    __shared__ int s_need;
    __shared__ int s_cnt;

    int n = g_ncand[b]; if (n > CAP) n = CAP;
    int Kb = n < TOPKN ? n : TOPKN;
    const unsigned long long* cb = g_keys[b];

    unsigned int hx = 0;
    for (int i = t; i < n; i += 512) {
        unsigned int hi = (unsigned int)(cb[i] >> 32);
        if (hi > hx) hx = hi;
    }
#pragma unroll
    for (int o = 16; o; o >>= 1) {
        unsigned int v = __shfl_xor_sync(0xffffffffu, hx, o);
        if (v > hx) hx = v;
    }
    if ((t & 31) == 0) s_mx[t >> 5] = hx;
    __syncthreads();
    unsigned int hmax = s_mx[0];
#pragma unroll
    for (int w = 1; w < 16; w++) if (s_mx[w] > hmax) hmax = s_mx[w];
    const float thresh = 0.3f * finv(hmax);

    unsigned long long T = 0ull;
    if (Kb > 0) {
        if (t == 0) { s_prefix = 0ull; s_need = Kb; }
        __syncthreads();
        const int sh_arr[6] = {53, 42, 31, 20, 9, 0};
#pragma unroll 1
        for (int pass = 0; pass < 6; pass++) {
            const int sh = sh_arr[pass];
            const int width = (pass < 5) ? 11 : 9;
            const unsigned int mask = (1u << width) - 1u;
            for (int i = t; i < 2048; i += 512) hist[i] = 0;
            __syncthreads();
            unsigned long long pref = s_prefix;
            const int hb = sh + width;
            const bool all = (pass == 0);
            const unsigned long long ph = all ? 0ull : (pref >> hb);
            for (int i = t; i < n; i += 512) {
                unsigned long long k = cb[i];
                if (all || (k >> hb) == ph)
                    atomicAdd(&hist[(int)((k >> sh) & mask)], 1);
            }
            __syncthreads();
            int sth = hist[4 * t] + hist[4 * t + 1] + hist[4 * t + 2] + hist[4 * t + 3];
            s_sth[t] = sth;
            int wsum = sth;
#pragma unroll
            for (int o = 16; o; o >>= 1) wsum += __shfl_xor_sync(0xffffffffu, wsum, o);
            if ((t & 31) == 0) s_ws[t >> 5] = wsum;
            __syncthreads();
            if (t == 0) {
                int need = s_need, cum = 0, w, th, bin;
                for (w = 15; w > 0; w--) { int v = s_ws[w]; if (cum + v >= need) break; cum += v; }
                for (th = 31; th > 0; th--) { int v = s_sth[w * 32 + th]; if (cum + v >= need) break; cum += v; }
                int base = (w * 32 + th) * 4;
                for (bin = 3; bin > 0; bin--) { int v = hist[base + bin]; if (cum + v >= need) break; cum += v; }
                s_need = need - cum;
                s_prefix = pref | ((unsigned long long)(base + bin) << sh);
            }
            __syncthreads();
        }
        T = s_prefix;
    }

    if (t == 0) s_cnt = 0;
    __syncthreads();
    if (Kb > 0) {
        for (int i = t; i < n; i += 512) {
            unsigned long long k = cb[i];
            if (k >= T) {
                int p = atomicAdd(&s_cnt, 1);
                if (p < TOPKN) skeys[p] = k;
            }
        }
    }
    __syncthreads();
    int m = s_cnt < TOPKN ? s_cnt : TOPKN;
    if (t >= m) skeys[t] = 0ull;
    __syncthreads();

    for (int k = 2; k <= TOPKN; k <<= 1) {
        for (int j = k >> 1; j > 0; j >>= 1) {
            int ixj = t ^ j;
            if (ixj > t) {
                unsigned long long a = skeys[t], c = skeys[ixj];
                bool sw = ((t & k) == 0) ? (a < c) : (a > c);
                if (sw) { skeys[t] = c; skeys[ixj] = a; }
            }
            __syncthreads();
        }
    }

    unsigned long long key = skeys[t];
    bool valid = (key != 0ull) && (finv((unsigned int)(key >> 32)) >= thresh);
    if (valid) {
        unsigned int idx = ~((unsigned int)key);
        out[(size_t)b * HW + idx] = 1.0f;
        if (write_coords) {
            float* coords = out + (size_t)BATCH * HW;
            coords[((size_t)b * TOPKN + t) * 2 + 0] = (float)(idx >> 10);
            coords[((size_t)b * TOPKN + t) * 2 + 1] = (float)(idx & 1023u);
        }
    } else if (write_coords) {
        float* coords = out + (size_t)BATCH * HW;
        coords[((size_t)b * TOPKN + t) * 2 + 0] = -1.0f;
        coords[((size_t)b * TOPKN + t) * 2 + 1] = -1.0f;
    }

    __syncthreads();
    if (t == 0) g_ncand[b] = 0;   // self-reset so graph replay is deterministic
}

extern "C" void kernel_launch(void* const* d_in, const int* in_sizes, int n_in,
                              void* d_out, int out_size) {
    const float* im = (const float*)d_in[0];
    float* out = (float*)d_out;

    cudaMemsetAsync(d_out, 0, (size_t)out_size * sizeof(float));

    dim3 grid(W / 32, H / 32, BATCH);
    k1_response<<<grid, 256>>>(im);
    k2_nms<<<grid, 256>>>();

    int wc = (out_size >= BATCH * HW + BATCH * TOPKN * 2) ? 1 : 0;
    k3_topk<<<BATCH, 512>>>(out, wc);
}

// round 14
// speedup vs baseline: 1.1132x; 1.1132x over previous
#include <cuda_runtime.h>
#include <math_constants.h>

#define BATCH 16
#define H 1024
#define W 1024
#define HW (H * W)
#define TOPKN 512
#define CAP 131072
#define K3_SMKEYS 20480

static __device__ float g_scores[(size_t)BATCH * HW];
static __device__ int g_ncand[BATCH];
static __device__ unsigned long long g_keys[BATCH][CAP];

__device__ __forceinline__ unsigned int ford(float f) {
    unsigned int u = __float_as_uint(f);
    return (u & 0x80000000u) ? ~u : (u | 0x80000000u);
}
__device__ __forceinline__ float finv(unsigned int u) {
    u = (u & 0x80000000u) ? (u & 0x7fffffffu) : ~u;
    return __uint_as_float(u);
}
__device__ __forceinline__ float shi_tomasi(int A, int Bv, int C) {
    float fa = (float)A, fc = (float)C, fb = (float)Bv;
    float dd = __fsub_rn(fa, fc);
    float s  = __fadd_rn(__fmul_rn(dd, dd), __fmul_rn(__fmul_rn(4.0f, fb), fb));
    return 0.5f * __fsub_rn(__fadd_rn(fa, fc), __fsqrt_rn(s));
}

// ===========================================================================
// K1: separable response, smem-unioned, register-lean S3.
// ===========================================================================
__global__ __launch_bounds__(256, 6) void k1_response(const float* __restrict__ im) {
    const int b = blockIdx.z;
    const int tx0 = blockIdx.x * 32, ty0 = blockIdx.y * 32;
    __shared__ __align__(16) unsigned spq[38][41];
    __shared__ __align__(16) int shB[38][36];
    __shared__ __align__(16) int shC[38][36];
    __shared__ __align__(16) int uarea[1640];      // simg[40][41] (S1/S2) then shA[38][36] (S3/S4)
    int (*simg)[41] = (int(*)[41])uarea;
    int (*shA)[36]  = (int(*)[36])uarea;
    const int t = threadIdx.x;
    const float* imb = im + (size_t)b * HW;

    // S1: quantized image, zero outside domain
    for (int i = t; i < 1600; i += 256) {
        int r = i / 40, c = i % 40;
        int yy = ty0 - 4 + r, xx = tx0 - 4 + c;
        int v = 0;
        if ((unsigned)yy < H && (unsigned)xx < W)
            v = __float2int_rd(imb[yy * W + xx] * 255.0f);
        simg[r][c] = v;
    }
    __syncthreads();

    // S2: vertical smooth p and diff q, packed (q<<16)|(p&0xFFFF)
    for (int i = t; i < 1520; i += 256) {
        int r = i / 40, c = i % 40;
        int a = simg[r][c], m = simg[r + 1][c], d2 = simg[r + 2][c];
        int p = a + 2 * m + d2;
        int q = d2 - a;
        spq[r][c] = (unsigned)((q << 16) | (p & 0xFFFF));
    }
    __syncthreads();   // simg dead beyond this point; uarea becomes shA

    // S3: 304 tasks = 38 grad-rows x 8 col-chunks of 4 outputs
    for (int i = t; i < 304; i += 256) {
        int r = i >> 3;
        int j0 = (i & 7) << 2;
        int4 a4 = make_int4(0, 0, 0, 0), b4 = a4, c4 = a4;
        if ((unsigned)(ty0 - 3 + r) < H) {
            int gx[10], gy[10];
#pragma unroll
            for (int g = 0; g < 10; g++) {
                unsigned p0 = spq[r][j0 + g];
                unsigned p1 = spq[r][j0 + g + 1];
                unsigned p2 = spq[r][j0 + g + 2];
                int gxx = (int)(p2 & 0xFFFFu) - (int)(p0 & 0xFFFFu);
                int gyy = (((int)p0) >> 16) + 2 * (((int)p1) >> 16) + (((int)p2) >> 16);
                bool ok = ((unsigned)(tx0 - 3 + j0 + g) < W);
                gx[g] = ok ? gxx : 0;
                gy[g] = ok ? gyy : 0;
            }
            {   // A = gx*gx
                int s = gx[0]*gx[0] + gx[1]*gx[1] + gx[2]*gx[2] + gx[3]*gx[3]
                      + gx[4]*gx[4] + gx[5]*gx[5] + gx[6]*gx[6];
                a4.x = s; s += gx[7]*gx[7] - gx[0]*gx[0]; a4.y = s;
                s += gx[8]*gx[8] - gx[1]*gx[1]; a4.z = s;
                s += gx[9]*gx[9] - gx[2]*gx[2]; a4.w = s;
            }
            {   // B = gx*gy
                int s = gx[0]*gy[0] + gx[1]*gy[1] + gx[2]*gy[2] + gx[3]*gy[3]
                      + gx[4]*gy[4] + gx[5]*gy[5] + gx[6]*gy[6];
                b4.x = s; s += gx[7]*gy[7] - gx[0]*gy[0]; b4.y = s;
                s += gx[8]*gy[8] - gx[1]*gy[1]; b4.z = s;
                s += gx[9]*gy[9] - gx[2]*gy[2]; b4.w = s;
            }
            {   // C = gy*gy
                int s = gy[0]*gy[0] + gy[1]*gy[1] + gy[2]*gy[2] + gy[3]*gy[3]
                      + gy[4]*gy[4] + gy[5]*gy[5] + gy[6]*gy[6];
                c4.x = s; s += gy[7]*gy[7] - gy[0]*gy[0]; c4.y = s;
                s += gy[8]*gy[8] - gy[1]*gy[1]; c4.z = s;
                s += gy[9]*gy[9] - gy[2]*gy[2]; c4.w = s;
            }
        }
        *(int4*)&shA[r][j0] = a4;
        *(int4*)&shB[r][j0] = b4;
        *(int4*)&shC[r][j0] = c4;
    }
    __syncthreads();

    // S4: vertical 7-sum, 4 outputs/thread
    {
        int r = t >> 3;
        int j0 = (t & 7) << 2;
        int sa0 = 0, sa1 = 0, sa2 = 0, sa3 = 0;
        int sb0 = 0, sb1 = 0, sb2 = 0, sb3 = 0;
        int sc0 = 0, sc1 = 0, sc2 = 0, sc3 = 0;
#pragma unroll
        for (int k = 0; k < 7; k++) {
            int4 a4 = *(const int4*)&shA[r + k][j0];
            int4 b4 = *(const int4*)&shB[r + k][j0];
            int4 c4 = *(const int4*)&shC[r + k][j0];
            sa0 += a4.x; sa1 += a4.y; sa2 += a4.z; sa3 += a4.w;
            sb0 += b4.x; sb1 += b4.y; sb2 += b4.z; sb3 += b4.w;
            sc0 += c4.x; sc1 += c4.y; sc2 += c4.z; sc3 += c4.w;
        }
        float4 o;
        o.x = shi_tomasi(sa0, sb0, sc0);
        o.y = shi_tomasi(sa1, sb1, sc1);
        o.z = shi_tomasi(sa2, sb2, sc2);
        o.w = shi_tomasi(sa3, sb3, sc3);
        *(float4*)(g_scores + (size_t)b * HW + (size_t)(ty0 + r) * W + tx0 + j0) = o;
    }
}

// ===========================================================================
// K2: pyramid NMS. Interior tiles use float4 unclamped loads (88% of tiles);
// boundary tiles use clamped scalars. sr is 48 cols based at X0-8.
//   h3[r][x] = max(sr[r][x..x+2])      (x = col-1 shifted, even-pair stores)
//   m3[r][x] = max(h3[r..r+2][x])  -> 3x3 max centered at sr[r+1][x+1]
//   pixel (r,c): center sr[r+7][c+8], 3x3max m3[r+6][c+7],
//   15x15 max = max m3[r+3di][c+1+3dj], di,dj in 0..4 (exact cover).
// ===========================================================================
#define SURVCAP 288
#define WINCAP 64

__global__ __launch_bounds__(256) void k2_nms() {
    const int b = blockIdx.z;
    const int X0 = blockIdx.x * 32, Y0 = blockIdx.y * 32;
    __shared__ __align__(16) float sr[46][48];
    __shared__ __align__(16) float h3[46][48];
    __shared__ __align__(16) float m3[44][48];
    __shared__ float sv[SURVCAP];
    __shared__ int spos[SURVCAP];
    __shared__ unsigned long long wk[WINCAP];
    __shared__ int scount;
    __shared__ int wcount;
    __shared__ int s_base;
    const int t = threadIdx.x;
    const float* rbase = g_scores + (size_t)b * HW;

    if (t == 0) { scount = 0; wcount = 0; }

    const bool interior = (X0 >= 32) && (X0 <= 960) && (Y0 >= 32) && (Y0 <= 960);
    if (interior) {
        const float* src = rbase + (size_t)(Y0 - 7) * W + (X0 - 8);
        for (int i = t; i < 552; i += 256) {          // 46 rows x 12 float4
            int r = i / 12, q = i - r * 12;
            *(float4*)&sr[r][q * 4] = *(const float4*)(src + (size_t)r * W + q * 4);
        }
    } else {
        for (int i = t; i < 46 * 48; i += 256) {
            int r = i / 48, c = i - (i / 48) * 48;
            int gy = min(max(Y0 - 7 + r, 0), H - 1);
            int gx = min(max(X0 - 8 + c, 0), W - 1);
            sr[r][c] = rbase[gy * W + gx];
        }
    }
    __syncthreads();

    // h3: 46 rows x 23 even pairs (cols 0..45)
    for (int i = t; i < 46 * 23; i += 256) {
        int r = i / 23, x = 2 * (i - (i / 23) * 23);
        float2 f0 = *(float2*)&sr[r][x];
        float2 f1 = *(float2*)&sr[r][x + 2];
        float h0 = fmaxf(f0.x, fmaxf(f0.y, f1.x));
        float h1 = fmaxf(f0.y, fmaxf(f1.x, f1.y));
        *(float2*)&h3[r][x] = make_float2(h0, h1);
    }
    __syncthreads();

    // m3: 44 rows x 23 even pairs
    for (int i = t; i < 44 * 23; i += 256) {
        int r = i / 23, x = 2 * (i - (i / 23) * 23);
        float2 a  = *(float2*)&h3[r][x];
        float2 bb = *(float2*)&h3[r + 1][x];
        float2 cc = *(float2*)&h3[r + 2][x];
        *(float2*)&m3[r][x] = make_float2(fmaxf(a.x, fmaxf(bb.x, cc.x)),
                                          fmaxf(a.y, fmaxf(bb.y, cc.y)));
    }
    __syncthreads();

    // prune (ballot-compacted): candidate must be >= its 3x3 max
#pragma unroll
    for (int it = 0; it < 4; it++) {
        int i = it * 256 + t;
        int r = i >> 5, c = i & 31;
        float v = sr[r + 7][c + 8];
        bool pred = (v >= m3[r + 6][c + 7]);
        unsigned mask = __ballot_sync(0xffffffffu, pred);
        int cnt = __popc(mask);
        int base = 0;
        if ((t & 31) == 0 && cnt > 0) base = atomicAdd(&scount, cnt);
        base = __shfl_sync(0xffffffffu, base, 0);
        if (pred) {
            int s = base + __popc(mask & ((1u << (t & 31)) - 1u));
            if (s < SURVCAP) { sv[s] = v; spos[s] = (r << 5) | c; }
        }
    }
    __syncthreads();

    // verify survivors vs exact 15x15 max
    int sc = scount < SURVCAP ? scount : SURVCAP;
    int iters = (sc + 255) >> 8;
    for (int it = 0; it < iters; it++) {
        int i = it * 256 + t;
        bool win = false;
        float v = 0.0f; int r = 0, c = 0;
        if (i < sc) {
            v = sv[i];
            int rc = spos[i];
            r = rc >> 5; c = rc & 31;
            float m = -CUDART_INF_F;
#pragma unroll
            for (int di = 0; di < 5; di++)
#pragma unroll
                for (int dj = 0; dj < 5; dj++)
                    m = fmaxf(m, m3[r + 3 * di][c + 1 + 3 * dj]);
            win = (v >= m);
        }
        unsigned mask = __ballot_sync(0xffffffffu, win);
        int cnt = __popc(mask);
        int base = 0;
        if ((t & 31) == 0 && cnt > 0) base = atomicAdd(&wcount, cnt);
        base = __shfl_sync(0xffffffffu, base, 0);
        if (win) {
            int w = base + __popc(mask & ((1u << (t & 31)) - 1u));
            if (w < WINCAP) {
                unsigned int idx = (unsigned)((Y0 + r) * W + (X0 + c));
                wk[w] = ((unsigned long long)ford(v) << 32) | (unsigned int)(~idx);
            }
        }
    }
    __syncthreads();

    int nw = wcount < WINCAP ? wcount : WINCAP;
    if (t == 0 && nw > 0) s_base = atomicAdd(&g_ncand[b], nw);
    __syncthreads();
    if (nw > 0) {
        int base = s_base;
        for (int i = t; i < nw; i += 256) {
            int slot = base + i;
            if (slot < CAP) g_keys[b][slot] = wk[i];
        }
    }
}

// ===========================================================================
// K3: keys staged in dynamic smem; max -> thresh; 6-pass histogram radix
// select; bitonic sort; threshold at output; counter self-reset.
// ===========================================================================
__global__ __launch_bounds__(512) void k3_topk(float* __restrict__ out, int write_coords) {
    extern __shared__ unsigned long long smkeys[];   // K3_SMKEYS entries
    const int b = blockIdx.x;
    const int t = threadIdx.x;
    __shared__ int hist[2048];
    __shared__ int s_sth[512];
    __shared__ int s_ws[16];
    __shared__ unsigned int s_mx[16];
    __shared__ unsigned long long skeys[TOPKN];
    __shared__ unsigned long long s_prefix;
    __shared__ int s_need;
    __shared__ int s_cnt;

    int n = g_ncand[b]; if (n > CAP) n = CAP;
    int Kb = n < TOPKN ? n : TOPKN;
    const unsigned long long* gk = g_keys[b];
    const bool use_sm = (n <= K3_SMKEYS);

    // copy keys to smem (if they fit) while computing the max value
    unsigned int hx = 0;
    for (int i = t; i < n; i += 512) {
        unsigned long long k = gk[i];
        if (use_sm) smkeys[i] = k;
        unsigned int hi = (unsigned int)(k >> 32);
        if (hi > hx) hx = hi;
    }
#pragma unroll
    for (int o = 16; o; o >>= 1) {
        unsigned int v = __shfl_xor_sync(0xffffffffu, hx, o);
        if (v > hx) hx = v;
    }
    if ((t & 31) == 0) s_mx[t >> 5] = hx;
    __syncthreads();
    unsigned int hmax = s_mx[0];
#pragma unroll
    for (int w = 1; w < 16; w++) if (s_mx[w] > hmax) hmax = s_mx[w];
    const float thresh = 0.3f * finv(hmax);
    const unsigned long long* cb = use_sm ? smkeys : gk;

    unsigned long long T = 0ull;
    if (Kb > 0) {
        if (t == 0) { s_prefix = 0ull; s_need = Kb; }
        __syncthreads();
        const int sh_arr[6] = {53, 42, 31, 20, 9, 0};
#pragma unroll 1
        for (int pass = 0; pass < 6; pass++) {
            const int sh = sh_arr[pass];
            const int width = (pass < 5) ? 11 : 9;
            const unsigned int mask = (1u << width) - 1u;
            for (int i = t; i < 2048; i += 512) hist[i] = 0;
            __syncthreads();
            unsigned long long pref = s_prefix;
            const int hb = sh + width;
            const bool all = (pass == 0);
            const unsigned long long ph = all ? 0ull : (pref >> hb);
            for (int i = t; i < n; i += 512) {
                unsigned long long k = cb[i];
                if (all || (k >> hb) == ph)
                    atomicAdd(&hist[(int)((k >> sh) & mask)], 1);
            }
            __syncthreads();
            int sth = hist[4 * t] + hist[4 * t + 1] + hist[4 * t + 2] + hist[4 * t + 3];
            s_sth[t] = sth;
            int wsum = sth;
#pragma unroll
            for (int o = 16; o; o >>= 1) wsum += __shfl_xor_sync(0xffffffffu, wsum, o);
            if ((t & 31) == 0) s_ws[t >> 5] = wsum;
            __syncthreads();
            if (t == 0) {
                int need = s_need, cum = 0, w, th, bin;
                for (w = 15; w > 0; w--) { int v = s_ws[w]; if (cum + v >= need) break; cum += v; }
                for (th = 31; th > 0; th--) { int v = s_sth[w * 32 + th]; if (cum + v >= need) break; cum += v; }
                int base = (w * 32 + th) * 4;
                for (bin = 3; bin > 0; bin--) { int v = hist[base + bin]; if (cum + v >= need) break; cum += v; }
                s_need = need - cum;
                s_prefix = pref | ((unsigned long long)(base + bin) << sh);
            }
            __syncthreads();
        }
        T = s_prefix;
    }

    if (t == 0) s_cnt = 0;
    __syncthreads();
    if (Kb > 0) {
        for (int i = t; i < n; i += 512) {
            unsigned long long k = cb[i];
            if (k >= T) {
                int p = atomicAdd(&s_cnt, 1);
                if (p < TOPKN) skeys[p] = k;
            }
        }
    }
    __syncthreads();
    int m = s_cnt < TOPKN ? s_cnt : TOPKN;
    if (t >= m) skeys[t] = 0ull;
    __syncthreads();

    for (int k = 2; k <= TOPKN; k <<= 1) {
        for (int j = k >> 1; j > 0; j >>= 1) {
            int ixj = t ^ j;
            if (ixj > t) {
                unsigned long long a = skeys[t], c = skeys[ixj];
                bool sw = ((t & k) == 0) ? (a < c) : (a > c);
                if (sw) { skeys[t] = c; skeys[ixj] = a; }
            }
            __syncthreads();
        }
    }

    unsigned long long key = skeys[t];
    bool valid = (key != 0ull) && (finv((unsigned int)(key >> 32)) >= thresh);
    if (valid) {
        unsigned int idx = ~((unsigned int)key);
        out[(size_t)b * HW + idx] = 1.0f;
        if (write_coords) {
            float* coords = out + (size_t)BATCH * HW;
            coords[((size_t)b * TOPKN + t) * 2 + 0] = (float)(idx >> 10);
            coords[((size_t)b * TOPKN + t) * 2 + 1] = (float)(idx & 1023u);
        }
    } else if (write_coords) {
        float* coords = out + (size_t)BATCH * HW;
        coords[((size_t)b * TOPKN + t) * 2 + 0] = -1.0f;
        coords[((size_t)b * TOPKN + t) * 2 + 1] = -1.0f;
    }

    __syncthreads();
    if (t == 0) g_ncand[b] = 0;   // self-reset so graph replay is deterministic
}

extern "C" void kernel_launch(void* const* d_in, const int* in_sizes, int n_in,
                              void* d_out, int out_size) {
    const float* im = (const float*)d_in[0];
    float* out = (float*)d_out;

    cudaFuncSetAttribute(k3_topk, cudaFuncAttributeMaxDynamicSharedMemorySize,
                         K3_SMKEYS * 8);

    cudaMemsetAsync(d_out, 0, (size_t)out_size * sizeof(float));

    dim3 grid(W / 32, H / 32, BATCH);
    k1_response<<<grid, 256>>>(im);
    k2_nms<<<grid, 256>>>();

    int wc = (out_size >= BATCH * HW + BATCH * TOPKN * 2) ? 1 : 0;
    k3_topk<<<BATCH, 512, K3_SMKEYS * 8>>>(out, wc);
}